// round 7
// baseline (speedup 1.0000x reference)
#include <cuda_runtime.h>
#include <cstdint>

#define SEQ     256
#define BATCH   512
#define IN_DIM  256
#define HDIM    8
#define DIN     264          // IN_DIM + HDIM
#define NROWS   (SEQ * BATCH)

// Scratch: pre-activations, bias folded in.
// Layout: zx[(t*BATCH + b)*32 + (g*8 + q)]  (column = lane in both roles)
// Padded one t-row so the recur prefetch never reads OOB.
__device__ __align__(16) float g_zx[(size_t)(NROWS + BATCH) * 32];

// Ready flags: one per gemm tile (64 rows). fidx = t*8 + oct, oct = b>>6.
// [0,2048) = real flags, [2048,2304) = pad preset to 1 (for t+1/t+2 >= SEQ).
#define NFLAG_REAL 2048
#define NFLAG_PAD  2304
__device__ unsigned g_flag[NFLAG_PAD];

typedef unsigned long long ull;

__device__ __forceinline__ void ffma2(ull &d, ull a, ull b) {
    asm("fma.rn.f32x2 %0, %1, %2, %0;" : "+l"(d) : "l"(a), "l"(b));
}
__device__ __forceinline__ float tanh_approx(float x) {
    float y; asm("tanh.approx.f32 %0, %1;" : "=f"(y) : "f"(x)); return y;
}
__device__ __forceinline__ void cpasync16(void* dst, const void* src) {
    unsigned ds = (unsigned)__cvta_generic_to_shared(dst);
    asm volatile("cp.async.cg.shared.global [%0], [%1], 16;" :: "r"(ds), "l"(src));
}
__device__ __forceinline__ void cp_commit() { asm volatile("cp.async.commit_group;"); }
template <int N> __device__ __forceinline__ void cp_wait() {
    asm volatile("cp.async.wait_group %0;" :: "n"(N));
}
__device__ __forceinline__ unsigned ld_acq(const unsigned* p) {
    unsigned v; asm volatile("ld.acquire.gpu.global.b32 %0, [%1];" : "=r"(v) : "l"(p)); return v;
}
__device__ __forceinline__ void st_rel(unsigned* p, unsigned v) {
    asm volatile("st.release.gpu.global.b32 [%0], %1;" :: "l"(p), "r"(v));
}
__device__ __forceinline__ void wait_flag(int fi) {
    unsigned r = ld_acq(&g_flag[fi]);
    while (r == 0) { __nanosleep(64); r = ld_acq(&g_flag[fi]); }
}

__global__ void init_flags() {
    int i = blockIdx.x * blockDim.x + threadIdx.x;
    if (i < NFLAG_PAD) g_flag[i] = (i < NFLAG_REAL) ? 0u : 1u;
}

// ---------------------------------------------------------------------------
// Fused kernel. Blocks 0..63: recur (8 warps = 8 batch elems each, persistent,
// spin on flags). Blocks 64..2111: gemm tiles of 64 rows (all of one t-octant),
// publishing st.release flag on completion. Shared memory is a union so the
// block footprint stays at 48KB (static limit, 4 blocks/SM by smem).
// ---------------------------------------------------------------------------
#define GEMM_BLOCKS 2048
#define RECUR_BLOCKS 64
#define KCH    32
#define NCHUNK 8

union SmemU {
    struct { float w_s[32 * 256]; float xs[2][64 * 32]; } g;   // 32KB + 16KB
    float ex[8][80];                                            // 2.5KB
};

__global__ void __launch_bounds__(256)
qlstm_fused(const float* __restrict__ x,
            const float* __restrict__ Wf, const float* __restrict__ bf,
            const float* __restrict__ Wi, const float* __restrict__ bi,
            const float* __restrict__ Wu, const float* __restrict__ bu,
            const float* __restrict__ Wo, const float* __restrict__ bo,
            const float* __restrict__ pf, const float* __restrict__ pi_,
            const float* __restrict__ pu, const float* __restrict__ po,
            float* __restrict__ out)
{
    __shared__ __align__(16) SmemU sm;

    const int tid  = threadIdx.x;
    const int lane = tid & 31;

    if (blockIdx.x >= RECUR_BLOCKS) {
        // ================= GEMM role: 64 rows = tile gb ====================
        const int gb   = blockIdx.x - RECUR_BLOCKS;
        const int warp = tid >> 5;
        const int row0  = gb * 64;
        const int wrow0 = warp * 8;

        float* w_s = sm.g.w_s;

        // Stage W x-part: 32 rows x 64 16B-slots = 2048, 8 per thread, swizzled.
        #pragma unroll
        for (int i = 0; i < 8; i++) {
            int idx = tid + 256 * i;
            int o = idx >> 6, s = idx & 63;
            int sw = (s & ~7) | ((s & 7) ^ (o & 7));
            int g = o >> 3, q = o & 7;
            const float* base = (g == 0 ? Wf : (g == 1 ? Wi : (g == 2 ? Wu : Wo)));
            cpasync16(&w_s[o * 256 + sw * 4], base + q * DIN + s * 4);
        }

        auto load_x = [&](int kc, int buf) {
            #pragma unroll
            for (int i = 0; i < 2; i++) {
                int idx = tid + 256 * i;          // 512 slots: 64 rows x 8 slots
                int r = idx >> 3, s = idx & 7;
                cpasync16(&sm.g.xs[buf][r * 32 + s * 4],
                          x + (size_t)(row0 + r) * IN_DIM + kc * KCH + s * 4);
            }
        };

        load_x(0, 0); cp_commit();                // group: {W, x0}

        ull acc[8];
        #pragma unroll
        for (int r = 0; r < 8; r++) acc[r] = 0ULL;

        #pragma unroll 1
        for (int kc = 0; kc < NCHUNK; kc++) {
            if (kc < NCHUNK - 1) { load_x(kc + 1, (kc + 1) & 1); cp_commit(); }
            if (kc < NCHUNK - 1) cp_wait<1>(); else cp_wait<0>();
            __syncthreads();

            ull wreg[16];
            #pragma unroll
            for (int j = 0; j < 8; j++) {
                int s  = kc * 8 + j;
                int sw = (s & ~7) | ((s & 7) ^ (lane & 7));
                ulonglong2 wv = *reinterpret_cast<const ulonglong2*>(&w_s[lane * 256 + sw * 4]);
                wreg[2 * j] = wv.x; wreg[2 * j + 1] = wv.y;
            }

            const float* xb = sm.g.xs[kc & 1];
            #pragma unroll
            for (int r = 0; r < 8; r++) {
                const ulonglong2* xp = reinterpret_cast<const ulonglong2*>(xb + (wrow0 + r) * 32);
                #pragma unroll
                for (int j = 0; j < 8; j++) {
                    ulonglong2 xv = xp[j];         // full-warp broadcast LDS.128
                    ffma2(acc[r], xv.x, wreg[2 * j]);
                    ffma2(acc[r], xv.y, wreg[2 * j + 1]);
                }
            }
            __syncthreads();
        }

        const int g = lane >> 3, q = lane & 7;
        const float bias = (g == 0 ? bf : (g == 1 ? bi : (g == 2 ? bu : bo)))[q];

        #pragma unroll
        for (int r = 0; r < 8; r++) {
            float2 p = *reinterpret_cast<float2*>(&acc[r]);
            g_zx[(size_t)(row0 + wrow0 + r) * 32 + lane] = p.x + p.y + bias;
        }

        __syncthreads();                           // all stores issued
        if (tid == 0) st_rel(&g_flag[gb], 1u);     // fidx == gb == t*8 + oct
    } else {
        // ================= RECUR role: 8 chains per block ==================
        const int wid = tid >> 5;
        const int b   = blockIdx.x * 8 + wid;
        const int oct = b >> 6;
        const int g = lane >> 3, q = lane & 7;

        float* cvrow = &sm.ex[wid][0];
        float* arow  = &sm.ex[wid][32];
        float* hrow  = &sm.ex[wid][64];

        const float* W = (g == 0 ? Wf : (g == 1 ? Wi : (g == 2 ? Wu : Wo))) + q * DIN + IN_DIM;
        const float* p = (g == 0 ? pf : (g == 1 ? pi_ : (g == 2 ? pu : po)));

        float Whr[8];
        #pragma unroll
        for (int j = 0; j < 8; j++) Whr[j] = W[j];

        float cth = __cosf(p[q]);
        if (g != 2 && q == 0) cth *= 0.5f;         // sigmoid 0.5x folded into prefix
        const float s2 = (g == 2) ? 1.f : 0.5f;
        const float s3 = (g == 2) ? 0.f : 0.5f;

        const bool p1 = (q >= 1), p2 = (q >= 2), p3 = (q >= 3),
                   p4 = (q >= 4), p5 = (q >= 5), p6 = (q >= 6), p7 = (q >= 7);

        const float* zp = g_zx + (size_t)b * 32 + lane;
        const size_t zstr = (size_t)BATCH * 32;

        float* sp     = out + (size_t)b * HDIM + q;
        float* hx_out = out + (size_t)SEQ * BATCH * HDIM;
        float* cx_out = hx_out + (size_t)BATCH * HDIM;

        float h0=0.f,h1=0.f,h2r=0.f,h3=0.f,h4=0.f,h5=0.f,h6=0.f,h7=0.f;
        float c = 0.f, hnew = 0.f;

        wait_flag(oct);            // t=0 tile ready
        float zcur = zp[0];
        wait_flag(8 + oct);        // t=1 tile ready (for first prefetch)

        #pragma unroll 2
        for (int t = 0; t < SEQ; t++) {
            float zn = zp[(size_t)(t + 1) * zstr];   // flag(t+1) already ensured
            wait_flag((t + 2) * 8 + oct);            // ensure for NEXT prefetch (pad for t+2>=SEQ)

            // recurrent dot, tree-shaped
            float s01 = fmaf(h1, Whr[1], h0 * Whr[0]);
            float s23 = fmaf(h3, Whr[3], h2r * Whr[2]);
            float s45 = fmaf(h5, Whr[5], h4 * Whr[4]);
            float s67 = fmaf(h7, Whr[7], h6 * Whr[6]);
            float z = zcur + ((s01 + s23) + (s45 + s67));

            float cv = __cosf(z) * cth;

            // round 1: share cos values within gate group
            cvrow[lane] = cv;
            __syncwarp();
            float4 va = *reinterpret_cast<const float4*>(cvrow + g * 8);
            float4 vb = *reinterpret_cast<const float4*>(cvrow + g * 8 + 4);

            float u1 = p1 ? va.y : 1.f, u2 = p2 ? va.z : 1.f, u3 = p3 ? va.w : 1.f;
            float u4 = p4 ? vb.x : 1.f, u5 = p5 ? vb.y : 1.f, u6 = p6 ? vb.z : 1.f;
            float u7 = p7 ? vb.w : 1.f;
            float pr = ((va.x * u1) * (u2 * u3)) * ((u4 * u5) * (u6 * u7));

            float th = tanh_approx(pr);
            float a  = fmaf(s2, th, s3);

            // round 2: gather (f,i,u,o) for my qubit in one LDS.128
            arow[q * 4 + g] = a;
            __syncwarp();
            float4 fiuo = *reinterpret_cast<const float4*>(arow + q * 4);

            c    = fmaf(fiuo.x, c, fiuo.y * fiuo.z);
            hnew = fiuo.w * tanh_approx(c);

            // round 3: broadcast h vector
            hrow[q] = hnew;
            __syncwarp();
            float4 ha = *reinterpret_cast<const float4*>(hrow);
            float4 hb = *reinterpret_cast<const float4*>(hrow + 4);
            h0 = ha.x; h1 = ha.y; h2r = ha.z; h3 = ha.w;
            h4 = hb.x; h5 = hb.y; h6 = hb.z; h7 = hb.w;

            sp[(size_t)t * (BATCH * HDIM)] = hnew;   // 4x same-addr dup, same value
            zcur = zn;
        }

        hx_out[(size_t)b * HDIM + q] = hnew;
        cx_out[(size_t)b * HDIM + q] = c;
    }
}

extern "C" void kernel_launch(void* const* d_in, const int* in_sizes, int n_in,
                              void* d_out, int out_size) {
    const float* inputs = (const float*)d_in[0];
    const float* Wf = (const float*)d_in[1];  const float* bf = (const float*)d_in[2];
    const float* Wi = (const float*)d_in[3];  const float* bi = (const float*)d_in[4];
    const float* Wu = (const float*)d_in[5];  const float* bu = (const float*)d_in[6];
    const float* Wo = (const float*)d_in[7];  const float* bo = (const float*)d_in[8];
    const float* pf  = (const float*)d_in[9];
    const float* pi_ = (const float*)d_in[10];
    const float* pu  = (const float*)d_in[11];
    const float* po  = (const float*)d_in[12];
    float* out = (float*)d_out;

    init_flags<<<9, 256>>>();
    qlstm_fused<<<RECUR_BLOCKS + GEMM_BLOCKS, 256>>>(
        inputs, Wf, bf, Wi, bi, Wu, bu, Wo, bo, pf, pi_, pu, po, out);
}

// round 8
// speedup vs baseline: 1.2192x; 1.2192x over previous
#include <cuda_runtime.h>
#include <cstdint>

#define SEQ     256
#define BATCH   512
#define IN_DIM  256
#define HDIM    8
#define DIN     264          // IN_DIM + HDIM
#define NROWS   (SEQ * BATCH)

// Scratch: pre-activations, bias folded in.
// Layout: zx[(t*BATCH + b)*32 + (g*8 + q)]  (column = lane in both roles)
// Padded one t-row so the recur prefetch never reads OOB.
__device__ __align__(16) float g_zx[(size_t)(NROWS + BATCH) * 32];

// Ready flags: one per gemm tile (64 rows). fidx = t*8 + oct, oct = b>>6.
// [0,2048) = real flags, [2048,2304) = pad preset to 1 (t >= SEQ).
#define NFLAG_REAL 2048
#define NFLAG_PAD  2304
__device__ unsigned g_flag[NFLAG_PAD];

typedef unsigned long long ull;

__device__ __forceinline__ void ffma2(ull &d, ull a, ull b) {
    asm("fma.rn.f32x2 %0, %1, %2, %0;" : "+l"(d) : "l"(a), "l"(b));
}
__device__ __forceinline__ float tanh_approx(float x) {
    float y; asm("tanh.approx.f32 %0, %1;" : "=f"(y) : "f"(x)); return y;
}
__device__ __forceinline__ void cpasync16(void* dst, const void* src) {
    unsigned ds = (unsigned)__cvta_generic_to_shared(dst);
    asm volatile("cp.async.cg.shared.global [%0], [%1], 16;" :: "r"(ds), "l"(src));
}
__device__ __forceinline__ void cp_commit() { asm volatile("cp.async.commit_group;"); }
template <int N> __device__ __forceinline__ void cp_wait() {
    asm volatile("cp.async.wait_group %0;" :: "n"(N));
}
__device__ __forceinline__ unsigned ld_acq(const unsigned* p) {
    unsigned v; asm volatile("ld.acquire.gpu.global.b32 %0, [%1];" : "=r"(v) : "l"(p)); return v;
}
__device__ __forceinline__ unsigned ld_rlx(const unsigned* p) {
    unsigned v; asm volatile("ld.relaxed.gpu.global.b32 %0, [%1];" : "=r"(v) : "l"(p)); return v;
}
__device__ __forceinline__ void st_rel(unsigned* p, unsigned v) {
    asm volatile("st.release.gpu.global.b32 [%0], %1;" :: "l"(p), "r"(v));
}
__device__ __forceinline__ void fence_acq() {
    asm volatile("fence.acq_rel.gpu;" ::: "memory");
}

__global__ void init_flags() {
    int i = blockIdx.x * blockDim.x + threadIdx.x;
    if (i < NFLAG_PAD) g_flag[i] = (i < NFLAG_REAL) ? 0u : 1u;
}

// ---------------------------------------------------------------------------
// Fused kernel. Blocks 0..63: recur (8 warps = 8 batch elems each, persistent,
// windowed flag verification). Blocks 64..2111: gemm tiles of 64 rows,
// publishing st.release flag on completion.
// ---------------------------------------------------------------------------
#define GEMM_BLOCKS 2048
#define RECUR_BLOCKS 64
#define KCH    32
#define NCHUNK 8

union SmemU {
    struct { float w_s[32 * 256]; float xs[2][64 * 32]; } g;   // 32KB + 16KB
    float ex[8][80];                                            // 2.5KB
};

__global__ void __launch_bounds__(256)
qlstm_fused(const float* __restrict__ x,
            const float* __restrict__ Wf, const float* __restrict__ bf,
            const float* __restrict__ Wi, const float* __restrict__ bi,
            const float* __restrict__ Wu, const float* __restrict__ bu,
            const float* __restrict__ Wo, const float* __restrict__ bo,
            const float* __restrict__ pf, const float* __restrict__ pi_,
            const float* __restrict__ pu, const float* __restrict__ po,
            float* __restrict__ out)
{
    __shared__ __align__(16) SmemU sm;

    const int tid  = threadIdx.x;
    const int lane = tid & 31;

    if (blockIdx.x >= RECUR_BLOCKS) {
        // ================= GEMM role: 64 rows = tile gb ====================
        const int gb   = blockIdx.x - RECUR_BLOCKS;
        const int warp = tid >> 5;
        const int row0  = gb * 64;
        const int wrow0 = warp * 8;

        float* w_s = sm.g.w_s;

        #pragma unroll
        for (int i = 0; i < 8; i++) {
            int idx = tid + 256 * i;
            int o = idx >> 6, s = idx & 63;
            int sw = (s & ~7) | ((s & 7) ^ (o & 7));
            int g = o >> 3, q = o & 7;
            const float* base = (g == 0 ? Wf : (g == 1 ? Wi : (g == 2 ? Wu : Wo)));
            cpasync16(&w_s[o * 256 + sw * 4], base + q * DIN + s * 4);
        }

        auto load_x = [&](int kc, int buf) {
            #pragma unroll
            for (int i = 0; i < 2; i++) {
                int idx = tid + 256 * i;          // 512 slots: 64 rows x 8 slots
                int r = idx >> 3, s = idx & 7;
                cpasync16(&sm.g.xs[buf][r * 32 + s * 4],
                          x + (size_t)(row0 + r) * IN_DIM + kc * KCH + s * 4);
            }
        };

        load_x(0, 0); cp_commit();                // group: {W, x0}

        ull acc[8];
        #pragma unroll
        for (int r = 0; r < 8; r++) acc[r] = 0ULL;

        #pragma unroll 1
        for (int kc = 0; kc < NCHUNK; kc++) {
            if (kc < NCHUNK - 1) { load_x(kc + 1, (kc + 1) & 1); cp_commit(); }
            if (kc < NCHUNK - 1) cp_wait<1>(); else cp_wait<0>();
            __syncthreads();

            ull wreg[16];
            #pragma unroll
            for (int j = 0; j < 8; j++) {
                int s  = kc * 8 + j;
                int sw = (s & ~7) | ((s & 7) ^ (lane & 7));
                ulonglong2 wv = *reinterpret_cast<const ulonglong2*>(&w_s[lane * 256 + sw * 4]);
                wreg[2 * j] = wv.x; wreg[2 * j + 1] = wv.y;
            }

            const float* xb = sm.g.xs[kc & 1];
            #pragma unroll
            for (int r = 0; r < 8; r++) {
                const ulonglong2* xp = reinterpret_cast<const ulonglong2*>(xb + (wrow0 + r) * 32);
                #pragma unroll
                for (int j = 0; j < 8; j++) {
                    ulonglong2 xv = xp[j];         // full-warp broadcast LDS.128
                    ffma2(acc[r], xv.x, wreg[2 * j]);
                    ffma2(acc[r], xv.y, wreg[2 * j + 1]);
                }
            }
            __syncthreads();
        }

        const int g = lane >> 3, q = lane & 7;
        const float bias = (g == 0 ? bf : (g == 1 ? bi : (g == 2 ? bu : bo)))[q];

        #pragma unroll
        for (int r = 0; r < 8; r++) {
            float2 p = *reinterpret_cast<float2*>(&acc[r]);
            g_zx[(size_t)(row0 + wrow0 + r) * 32 + lane] = p.x + p.y + bias;
        }

        __syncthreads();                           // block stores done (cta fence)
        if (tid == 0) st_rel(&g_flag[gb], 1u);     // fidx == gb == t*8 + oct
    } else {
        // ================= RECUR role: 8 chains per block ==================
        const int wid = tid >> 5;
        const int b   = blockIdx.x * 8 + wid;
        const int oct = b >> 6;
        const int g = lane >> 3, q = lane & 7;

        float* cvrow = &sm.ex[wid][0];
        float* arow  = &sm.ex[wid][32];
        float* hrow  = &sm.ex[wid][64];

        const float* W = (g == 0 ? Wf : (g == 1 ? Wi : (g == 2 ? Wu : Wo))) + q * DIN + IN_DIM;
        const float* p = (g == 0 ? pf : (g == 1 ? pi_ : (g == 2 ? pu : po)));

        float Whr[8];
        #pragma unroll
        for (int j = 0; j < 8; j++) Whr[j] = W[j];

        float cth = __cosf(p[q]);
        if (g != 2 && q == 0) cth *= 0.5f;         // sigmoid 0.5x folded into prefix
        const float s2 = (g == 2) ? 1.f : 0.5f;
        const float s3 = (g == 2) ? 0.f : 0.5f;

        const bool p1 = (q >= 1), p2 = (q >= 2), p3 = (q >= 3),
                   p4 = (q >= 4), p5 = (q >= 5), p6 = (q >= 6), p7 = (q >= 7);

        const float* zp = g_zx + (size_t)b * 32 + lane;
        const size_t zstr = (size_t)BATCH * 32;

        float* sp     = out + (size_t)b * HDIM + q;
        float* hx_out = out + (size_t)SEQ * BATCH * HDIM;
        float* cx_out = hx_out + (size_t)BATCH * HDIM;

        float h0=0.f,h1=0.f,h2r=0.f,h3=0.f,h4=0.f,h5=0.f,h6=0.f,h7=0.f;
        float c = 0.f, hnew = 0.f;

        // Windowed flag protocol. fv holds flags for t = w8+1 .. w8+8,
        // loaded one window EARLY so their latency is hidden by compute.
        unsigned fv[8];
        auto load_flags = [&](int w8) {            // flags for t = w8+1..w8+8
            #pragma unroll
            for (int i = 0; i < 8; i++)
                fv[i] = ld_rlx(&g_flag[(w8 + 1 + i) * 8 + oct]);
        };

        // prologue: t=0 flag (blocking acquire), then window-0 flags
        {
            unsigned r = ld_acq(&g_flag[oct]);
            while (r == 0) { __nanosleep(128); r = ld_acq(&g_flag[oct]); }
        }
        load_flags(0);
        float zcur = zp[0];

        #pragma unroll 1
        for (int w = 0; w < SEQ / 8; w++) {
            const int tw = w * 8;

            // verify window flags (usually already set; rare fallback poll)
            unsigned allv = fv[0] & fv[1] & fv[2] & fv[3] & fv[4] & fv[5] & fv[6] & fv[7];
            if (allv == 0) {
                #pragma unroll
                for (int i = 0; i < 8; i++) {
                    while (fv[i] == 0) {
                        __nanosleep(128);
                        fv[i] = ld_rlx(&g_flag[(tw + 1 + i) * 8 + oct]);
                    }
                }
            }
            fence_acq();                            // order flag reads before z reads
            if (w < SEQ / 8 - 1) load_flags(tw + 8); // prefetch next window's flags

            #pragma unroll
            for (int s = 0; s < 8; s++) {
                const int t = tw + s;
                float zn = zp[(size_t)(t + 1) * zstr];   // flag verified above

                // recurrent dot, tree-shaped
                float s01 = fmaf(h1, Whr[1], h0 * Whr[0]);
                float s23 = fmaf(h3, Whr[3], h2r * Whr[2]);
                float s45 = fmaf(h5, Whr[5], h4 * Whr[4]);
                float s67 = fmaf(h7, Whr[7], h6 * Whr[6]);
                float z = zcur + ((s01 + s23) + (s45 + s67));

                float cv = __cosf(z) * cth;

                // round 1: share cos values within gate group
                cvrow[lane] = cv;
                __syncwarp();
                float4 va = *reinterpret_cast<const float4*>(cvrow + g * 8);
                float4 vb = *reinterpret_cast<const float4*>(cvrow + g * 8 + 4);

                float u1 = p1 ? va.y : 1.f, u2 = p2 ? va.z : 1.f, u3 = p3 ? va.w : 1.f;
                float u4 = p4 ? vb.x : 1.f, u5 = p5 ? vb.y : 1.f, u6 = p6 ? vb.z : 1.f;
                float u7 = p7 ? vb.w : 1.f;
                float pr = ((va.x * u1) * (u2 * u3)) * ((u4 * u5) * (u6 * u7));

                float th = tanh_approx(pr);
                float a  = fmaf(s2, th, s3);

                // round 2: gather (f,i,u,o) for my qubit in one LDS.128
                arow[q * 4 + g] = a;
                __syncwarp();
                float4 fiuo = *reinterpret_cast<const float4*>(arow + q * 4);

                c    = fmaf(fiuo.x, c, fiuo.y * fiuo.z);
                hnew = fiuo.w * tanh_approx(c);

                // round 3: broadcast h vector
                hrow[q] = hnew;
                __syncwarp();
                float4 ha = *reinterpret_cast<const float4*>(hrow);
                float4 hb = *reinterpret_cast<const float4*>(hrow + 4);
                h0 = ha.x; h1 = ha.y; h2r = ha.z; h3 = ha.w;
                h4 = hb.x; h5 = hb.y; h6 = hb.z; h7 = hb.w;

                sp[(size_t)t * (BATCH * HDIM)] = hnew;   // 4x same-addr dup, same value
                zcur = zn;
            }
        }

        hx_out[(size_t)b * HDIM + q] = hnew;
        cx_out[(size_t)b * HDIM + q] = c;
    }
}

extern "C" void kernel_launch(void* const* d_in, const int* in_sizes, int n_in,
                              void* d_out, int out_size) {
    const float* inputs = (const float*)d_in[0];
    const float* Wf = (const float*)d_in[1];  const float* bf = (const float*)d_in[2];
    const float* Wi = (const float*)d_in[3];  const float* bi = (const float*)d_in[4];
    const float* Wu = (const float*)d_in[5];  const float* bu = (const float*)d_in[6];
    const float* Wo = (const float*)d_in[7];  const float* bo = (const float*)d_in[8];
    const float* pf  = (const float*)d_in[9];
    const float* pi_ = (const float*)d_in[10];
    const float* pu  = (const float*)d_in[11];
    const float* po  = (const float*)d_in[12];
    float* out = (float*)d_out;

    init_flags<<<9, 256>>>();
    qlstm_fused<<<RECUR_BLOCKS + GEMM_BLOCKS, 256>>>(
        inputs, Wf, bf, Wi, bi, Wu, bu, Wo, bo, pf, pi_, pu, po, out);
}